// round 1
// baseline (speedup 1.0000x reference)
#include <cuda_runtime.h>
#include <math.h>

#define D   64
#define MAXN 8192
#define BM  32
#define BN  64

// Scratch (allocation-free contract: __device__ globals)
__device__ __align__(16) float g_Qn[(size_t)MAXN * D];
__device__ __align__(16) float g_Kn[(size_t)MAXN * D];
__device__ float g_invsum[MAXN];

// Robustly turn the 1-element "hyper_c" input into a float:
// handles int32/int64 (low word) and a float32 bit-pattern fallback.
__device__ __forceinline__ float load_hyper_c(const int* hc) {
    int iv = hc[0];
    if (iv > 1000000 || iv < -1000000) return __int_as_float(iv);
    return (float)iv;
}

// ---------------------------------------------------------------------------
// Kernel 1: L2-normalize rows of Q and K into scratch. One warp per row.
// ---------------------------------------------------------------------------
__global__ void norm_kernel(const float* __restrict__ q,
                            const float* __restrict__ k,
                            int N, int M) {
    int gw   = (blockIdx.x * blockDim.x + threadIdx.x) >> 5;
    int lane = threadIdx.x & 31;
    if (gw >= N + M) return;

    const float* src;
    float* dst;
    if (gw < N) { src = q + (size_t)gw * D;        dst = g_Qn + (size_t)gw * D; }
    else        { size_t r = gw - N; src = k + r * D; dst = g_Kn + r * D; }

    float2 v = reinterpret_cast<const float2*>(src)[lane];
    float ss = v.x * v.x + v.y * v.y;
#pragma unroll
    for (int o = 16; o > 0; o >>= 1) ss += __shfl_xor_sync(0xffffffffu, ss, o);
    float inv = rsqrtf(ss);
    reinterpret_cast<float2*>(dst)[lane] = make_float2(v.x * inv, v.y * inv);
}

// ---------------------------------------------------------------------------
// Kernel 2: per block = strip of BM=32 query rows across all M keys.
//   Pass over M in BN=64 tiles:
//     S = Qn*Kn^T (smem GEMM, 4x4 microtile) -> e = exp(c*(s-1))
//     write e (unnormalized) to p region, accumulate rowsum, O += e@V.
//   End: O *= 1/rowsum, write res; publish 1/rowsum for the rescale pass.
// 128 threads: tx = tid&15 (4 cols each), ty = tid>>4 (4 rows each).
// ---------------------------------------------------------------------------
__global__ __launch_bounds__(128)
void strip_kernel(const float* __restrict__ Vg,
                  const int*   __restrict__ hc,
                  float* __restrict__ out_res,
                  float* __restrict__ out_p,
                  int N, int M) {
    __shared__ __align__(16) float QsT[D][BM];       // [k][r]
    __shared__ __align__(16) float KVs[D][BN + 4];   // K phase: [k][c]; V phase: [c][d]
    __shared__ __align__(16) float es [BM][BN + 4];  // exp tile [r][c]
    __shared__ float rowsum_s[BM];

    const int tid = threadIdx.x;
    const int tx  = tid & 15;
    const int ty  = tid >> 4;
    const int r0  = blockIdx.x * BM;
    const float c = load_hyper_c(hc);

    if (tid < BM) rowsum_s[tid] = 0.0f;

    // Load Q strip transposed: 32x64 floats = 512 float4, 4 per thread.
#pragma unroll
    for (int li = 0; li < 4; li++) {
        int fidx = tid + li * 128;        // 0..511
        int row  = fidx >> 4;             // 0..31
        int c4   = fidx & 15;             // 0..15
        float4 v = reinterpret_cast<const float4*>(g_Qn)[(size_t)(r0 + row) * (D / 4) + c4];
        QsT[c4 * 4 + 0][row] = v.x;
        QsT[c4 * 4 + 1][row] = v.y;
        QsT[c4 * 4 + 2][row] = v.z;
        QsT[c4 * 4 + 3][row] = v.w;
    }
    __syncthreads();

    float Oacc[4][4];
#pragma unroll
    for (int i = 0; i < 4; i++)
#pragma unroll
        for (int j = 0; j < 4; j++) Oacc[i][j] = 0.0f;
    float rs[4] = {0.f, 0.f, 0.f, 0.f};

    for (int m0 = 0; m0 < M; m0 += BN) {
        // ---- load K tile transposed: KsT[k][c] ----
#pragma unroll
        for (int li = 0; li < 8; li++) {
            int fidx = tid + li * 128;    // 0..1023
            int row  = fidx >> 4;         // m-local 0..63
            int c4   = fidx & 15;
            float4 v = reinterpret_cast<const float4*>(g_Kn)[(size_t)(m0 + row) * (D / 4) + c4];
            KVs[c4 * 4 + 0][row] = v.x;
            KVs[c4 * 4 + 1][row] = v.y;
            KVs[c4 * 4 + 2][row] = v.z;
            KVs[c4 * 4 + 3][row] = v.w;
        }
        __syncthreads();

        // ---- QK: S[r][c] = sum_k QsT[k][r] * KsT[k][c] ----
        float acc[4][4];
#pragma unroll
        for (int i = 0; i < 4; i++)
#pragma unroll
            for (int j = 0; j < 4; j++) acc[i][j] = 0.0f;

#pragma unroll 16
        for (int k = 0; k < D; k++) {
            float4 qv = *reinterpret_cast<const float4*>(&QsT[k][ty * 4]);
            float4 kv = *reinterpret_cast<const float4*>(&KVs[k][tx * 4]);
            acc[0][0] += qv.x * kv.x; acc[0][1] += qv.x * kv.y; acc[0][2] += qv.x * kv.z; acc[0][3] += qv.x * kv.w;
            acc[1][0] += qv.y * kv.x; acc[1][1] += qv.y * kv.y; acc[1][2] += qv.y * kv.z; acc[1][3] += qv.y * kv.w;
            acc[2][0] += qv.z * kv.x; acc[2][1] += qv.z * kv.y; acc[2][2] += qv.z * kv.z; acc[2][3] += qv.z * kv.w;
            acc[3][0] += qv.w * kv.x; acc[3][1] += qv.w * kv.y; acc[3][2] += qv.w * kv.z; acc[3][3] += qv.w * kv.w;
        }

        // ---- e = exp(c*(s-1)) [stable: cos<=1]; write p (unnormalized) ----
#pragma unroll
        for (int i = 0; i < 4; i++) {
            float4 ev;
            ev.x = __expf(c * (acc[i][0] - 1.0f));
            ev.y = __expf(c * (acc[i][1] - 1.0f));
            ev.z = __expf(c * (acc[i][2] - 1.0f));
            ev.w = __expf(c * (acc[i][3] - 1.0f));
            rs[i] += (ev.x + ev.y) + (ev.z + ev.w);
            int grow = r0 + ty * 4 + i;
            *reinterpret_cast<float4*>(out_p + (size_t)grow * M + m0 + tx * 4) = ev;
            *reinterpret_cast<float4*>(&es[ty * 4 + i][tx * 4]) = ev;
        }
        __syncthreads();

        // ---- load V tile natural: Vs[c][d] (reusing KVs) ----
#pragma unroll
        for (int li = 0; li < 8; li++) {
            int fidx = tid + li * 128;
            int row  = fidx >> 4;
            int c4   = fidx & 15;
            float4 v = reinterpret_cast<const float4*>(Vg)[(size_t)(m0 + row) * (D / 4) + c4];
            *reinterpret_cast<float4*>(&KVs[row][c4 * 4]) = v;
        }
        __syncthreads();

        // ---- PV: O[r][d] += sum_c e[r][c] * V[c][d] ----
#pragma unroll 16
        for (int cc = 0; cc < BN; cc++) {
            float4 vv = *reinterpret_cast<const float4*>(&KVs[cc][tx * 4]);
            float e0 = es[ty * 4 + 0][cc];
            float e1 = es[ty * 4 + 1][cc];
            float e2 = es[ty * 4 + 2][cc];
            float e3 = es[ty * 4 + 3][cc];
            Oacc[0][0] += e0 * vv.x; Oacc[0][1] += e0 * vv.y; Oacc[0][2] += e0 * vv.z; Oacc[0][3] += e0 * vv.w;
            Oacc[1][0] += e1 * vv.x; Oacc[1][1] += e1 * vv.y; Oacc[1][2] += e1 * vv.z; Oacc[1][3] += e1 * vv.w;
            Oacc[2][0] += e2 * vv.x; Oacc[2][1] += e2 * vv.y; Oacc[2][2] += e2 * vv.z; Oacc[2][3] += e2 * vv.w;
            Oacc[3][0] += e3 * vv.x; Oacc[3][1] += e3 * vv.y; Oacc[3][2] += e3 * vv.z; Oacc[3][3] += e3 * vv.w;
        }
        __syncthreads();
    }

    // ---- reduce rowsums across the 16 tx threads sharing each row ----
#pragma unroll
    for (int i = 0; i < 4; i++) atomicAdd(&rowsum_s[ty * 4 + i], rs[i]);
    __syncthreads();

    if (tid < BM) g_invsum[r0 + tid] = 1.0f / rowsum_s[tid];

#pragma unroll
    for (int i = 0; i < 4; i++) {
        float inv = 1.0f / rowsum_s[ty * 4 + i];
        float4 ov = make_float4(Oacc[i][0] * inv, Oacc[i][1] * inv,
                                Oacc[i][2] * inv, Oacc[i][3] * inv);
        *reinterpret_cast<float4*>(out_res + (size_t)(r0 + ty * 4 + i) * D + tx * 4) = ov;
    }
}

// ---------------------------------------------------------------------------
// Kernel 3: normalize the stored p region: p[row][:] *= 1/rowsum[row].
// Grid: (ceil(M/4/256), N), one float4 per thread.
// ---------------------------------------------------------------------------
__global__ void rescale_kernel(float* __restrict__ p, int M) {
    int row  = blockIdx.y;
    int col4 = blockIdx.x * blockDim.x + threadIdx.x;
    int m4   = M >> 2;
    if (col4 >= m4) return;
    float inv = g_invsum[row];
    float4* p4 = reinterpret_cast<float4*>(p) + (size_t)row * m4 + col4;
    float4 v = *p4;
    v.x *= inv; v.y *= inv; v.z *= inv; v.w *= inv;
    *p4 = v;
}

// ---------------------------------------------------------------------------
extern "C" void kernel_launch(void* const* d_in, const int* in_sizes, int n_in,
                              void* d_out, int out_size) {
    const float* q  = (const float*)d_in[0];
    const float* k  = (const float*)d_in[1];
    const float* v  = (const float*)d_in[2];
    const int*   hc = (const int*)d_in[3];

    int N = in_sizes[0] / D;
    int M = in_sizes[1] / D;

    float* out_res = (float*)d_out;                      // [N, D]
    float* out_p   = (float*)d_out + (size_t)N * D;      // [N, M]

    int rows = N + M;
    int norm_blocks = (rows * 32 + 255) / 256;
    norm_kernel<<<norm_blocks, 256>>>(q, k, N, M);

    strip_kernel<<<N / BM, 128>>>(v, hc, out_res, out_p, N, M);

    dim3 rg((M / 4 + 255) / 256, N);
    rescale_kernel<<<rg, 256>>>(out_p, M);
}

// round 2
// speedup vs baseline: 2.1428x; 2.1428x over previous
#include <cuda_runtime.h>
#include <math.h>

#define D    64
#define MAXN 8192
#define BM   32
#define BN   64

// Scratch (allocation-free contract: __device__ globals)
__device__ __align__(16) float g_Qn[(size_t)MAXN * D];
__device__ __align__(16) float g_Kn[(size_t)MAXN * D];
__device__ float g_invsum[MAXN];

// Robustly turn the 1-element "hyper_c" input into a float:
// handles int32/int64 (low word) and a float32 bit-pattern fallback.
__device__ __forceinline__ float load_hyper_c(const int* hc) {
    int iv = hc[0];
    if (iv > 1000000 || iv < -1000000) return __int_as_float(iv);
    return (float)iv;
}

__device__ __forceinline__ float to_tf32(float x) {
    float r;
    asm("cvt.rna.tf32.f32 %0, %1;" : "=f"(r) : "f"(x));
    return r;
}

// D += A*B, m16n8k8 tf32, A row-major frag (4 regs), B col-major frag (2 regs)
__device__ __forceinline__ void mma_tf32(float d[4], const float a[4], const float b[2]) {
    asm volatile(
        "mma.sync.aligned.m16n8k8.row.col.f32.tf32.tf32.f32 "
        "{%0,%1,%2,%3}, {%4,%5,%6,%7}, {%8,%9}, {%0,%1,%2,%3};\n"
        : "+f"(d[0]), "+f"(d[1]), "+f"(d[2]), "+f"(d[3])
        : "r"(__float_as_uint(a[0])), "r"(__float_as_uint(a[1])),
          "r"(__float_as_uint(a[2])), "r"(__float_as_uint(a[3])),
          "r"(__float_as_uint(b[0])), "r"(__float_as_uint(b[1])));
}

// ---------------------------------------------------------------------------
// Kernel 1: L2-normalize rows of Q and K into scratch. One warp per row.
// ---------------------------------------------------------------------------
__global__ void norm_kernel(const float* __restrict__ q,
                            const float* __restrict__ k,
                            int N, int M) {
    int gw   = (blockIdx.x * blockDim.x + threadIdx.x) >> 5;
    int lane = threadIdx.x & 31;
    if (gw >= N + M) return;

    const float* src;
    float* dst;
    if (gw < N) { src = q + (size_t)gw * D;        dst = g_Qn + (size_t)gw * D; }
    else        { size_t r = gw - N; src = k + r * D; dst = g_Kn + r * D; }

    float2 v = reinterpret_cast<const float2*>(src)[lane];
    float ss = v.x * v.x + v.y * v.y;
#pragma unroll
    for (int o = 16; o > 0; o >>= 1) ss += __shfl_xor_sync(0xffffffffu, ss, o);
    float inv = rsqrtf(ss);
    reinterpret_cast<float2*>(dst)[lane] = make_float2(v.x * inv, v.y * inv);
}

// ---------------------------------------------------------------------------
// Kernel 2: strip of BM=32 query rows across all M keys, tensor-core GEMMs.
// 4 warps arranged 2x2: wr = row half (16 rows), wc = col half (32 cols / d).
// Per BN=64 tile:  S = Qn*Kn^T (mma tf32) -> e=exp(c*(s-1)) -> Es smem
//                  -> write unnormalized p, O += E@V (mma tf32).
// K stride 68 / V stride 72 in a shared union buffer: both fragment access
// patterns conflict-free.
// ---------------------------------------------------------------------------
__global__ __launch_bounds__(128)
void strip_kernel(const float* __restrict__ Vg,
                  const int*   __restrict__ hc,
                  float* __restrict__ out_res,
                  float* __restrict__ out_p,
                  int N, int M) {
    __shared__ __align__(16) float Qs[BM * 68];
    __shared__ __align__(16) float KV[BN * 72];   // K phase stride 68, V phase stride 72
    __shared__ __align__(16) float Es[BM * 68];
    __shared__ float rowsum_s[BM];

    const int tid  = threadIdx.x;
    const int lane = tid & 31;
    const int wid  = tid >> 5;
    const int wr   = wid >> 1;   // 0..1
    const int wc   = wid & 1;    // 0..1
    const int g    = lane >> 2;  // 0..7
    const int t    = lane & 3;   // 0..3
    const int r0   = blockIdx.x * BM;
    const float c  = load_hyper_c(hc);

    if (tid < BM) rowsum_s[tid] = 0.0f;

    // Load Q strip (tf32-rounded): 32x64 = 512 float4
#pragma unroll
    for (int i = 0; i < 4; i++) {
        int fidx = tid + i * 128;
        int row  = fidx >> 4, c4 = fidx & 15;
        float4 v = reinterpret_cast<const float4*>(g_Qn)[(size_t)(r0 + row) * 16 + c4];
        float* dst = &Qs[row * 68 + c4 * 4];
        dst[0] = to_tf32(v.x); dst[1] = to_tf32(v.y);
        dst[2] = to_tf32(v.z); dst[3] = to_tf32(v.w);
    }
    __syncthreads();

    const int rlo = wr * 16 + g;
    const int rhi = rlo + 8;

    // Hoisted Q A-fragments (loop-invariant): 8 k-chunks x 4 regs
    float qa[8][4];
#pragma unroll
    for (int kc = 0; kc < 8; kc++) {
        qa[kc][0] = Qs[rlo * 68 + kc * 8 + t];
        qa[kc][1] = Qs[rhi * 68 + kc * 8 + t];
        qa[kc][2] = Qs[rlo * 68 + kc * 8 + t + 4];
        qa[kc][3] = Qs[rhi * 68 + kc * 8 + t + 4];
    }

    float oacc[4][4];
#pragma unroll
    for (int i = 0; i < 4; i++)
#pragma unroll
        for (int j = 0; j < 4; j++) oacc[i][j] = 0.0f;
    float rs_lo = 0.0f, rs_hi = 0.0f;

    for (int m0 = 0; m0 < M; m0 += BN) {
        // ---- load K tile, stride 68 ----
#pragma unroll
        for (int i = 0; i < 8; i++) {
            int fidx = tid + i * 128;
            int row  = fidx >> 4, c4 = fidx & 15;
            float4 v = reinterpret_cast<const float4*>(g_Kn)[(size_t)(m0 + row) * 16 + c4];
            float* dst = &KV[row * 68 + c4 * 4];
            dst[0] = to_tf32(v.x); dst[1] = to_tf32(v.y);
            dst[2] = to_tf32(v.z); dst[3] = to_tf32(v.w);
        }
        __syncthreads();

        // ---- QK: S[16][32] per warp via 8kc x 4nt mma ----
        float sacc[4][4];
#pragma unroll
        for (int i = 0; i < 4; i++)
#pragma unroll
            for (int j = 0; j < 4; j++) sacc[i][j] = 0.0f;

#pragma unroll
        for (int kc = 0; kc < 8; kc++) {
#pragma unroll
            for (int nt = 0; nt < 4; nt++) {
                int n0 = wc * 32 + nt * 8;
                float b[2];
                b[0] = KV[(n0 + g) * 68 + kc * 8 + t];       // B[k=t][n=g]
                b[1] = KV[(n0 + g) * 68 + kc * 8 + t + 4];   // B[k=t+4][n=g]
                mma_tf32(sacc[nt], qa[kc], b);
            }
        }

        // ---- exp + Es store + rowsum (C frag: (g,2t),(g,2t+1),(g+8,2t),(g+8,2t+1)) ----
#pragma unroll
        for (int nt = 0; nt < 4; nt++) {
            int col = wc * 32 + nt * 8 + 2 * t;
            float e0 = __expf(c * (sacc[nt][0] - 1.0f));
            float e1 = __expf(c * (sacc[nt][1] - 1.0f));
            float e2 = __expf(c * (sacc[nt][2] - 1.0f));
            float e3 = __expf(c * (sacc[nt][3] - 1.0f));
            rs_lo += e0 + e1;
            rs_hi += e2 + e3;
            *reinterpret_cast<float2*>(&Es[rlo * 68 + col]) = make_float2(e0, e1);
            *reinterpret_cast<float2*>(&Es[rhi * 68 + col]) = make_float2(e2, e3);
        }
        __syncthreads();   // Es complete; all QK reads of KV complete

        // ---- load V tile, stride 72; write unnormalized p from Es ----
#pragma unroll
        for (int i = 0; i < 8; i++) {
            int fidx = tid + i * 128;
            int row  = fidx >> 4, c4 = fidx & 15;
            float4 v = reinterpret_cast<const float4*>(Vg)[(size_t)(m0 + row) * 16 + c4];
            float* dst = &KV[row * 72 + c4 * 4];
            dst[0] = to_tf32(v.x); dst[1] = to_tf32(v.y);
            dst[2] = to_tf32(v.z); dst[3] = to_tf32(v.w);
        }
#pragma unroll
        for (int i = 0; i < 4; i++) {
            int fidx = tid + i * 128;
            int row  = fidx >> 4, c4 = fidx & 15;
            float4 ev = *reinterpret_cast<const float4*>(&Es[row * 68 + c4 * 4]);
            *reinterpret_cast<float4*>(out_p + (size_t)(r0 + row) * M + m0 + c4 * 4) = ev;
        }
        __syncthreads();

        // ---- PV: O[16][32] per warp += E @ V ----
#pragma unroll
        for (int kc = 0; kc < 8; kc++) {
            float a[4];
            a[0] = to_tf32(Es[rlo * 68 + kc * 8 + t]);
            a[1] = to_tf32(Es[rhi * 68 + kc * 8 + t]);
            a[2] = to_tf32(Es[rlo * 68 + kc * 8 + t + 4]);
            a[3] = to_tf32(Es[rhi * 68 + kc * 8 + t + 4]);
#pragma unroll
            for (int nt = 0; nt < 4; nt++) {
                int d0 = wc * 32 + nt * 8;
                float b[2];
                b[0] = KV[(kc * 8 + t) * 72 + d0 + g];       // B[k=t][n=g] = V[cc][d]
                b[1] = KV[(kc * 8 + t + 4) * 72 + d0 + g];
                mma_tf32(oacc[nt], a, b);
            }
        }
        __syncthreads();   // PV reads of KV/Es complete before next overwrite
    }

    // ---- rowsum reduction: over t within quad, then across col-warps ----
#pragma unroll
    for (int o = 1; o <= 2; o <<= 1) {
        rs_lo += __shfl_xor_sync(0xffffffffu, rs_lo, o);
        rs_hi += __shfl_xor_sync(0xffffffffu, rs_hi, o);
    }
    if (t == 0) {
        atomicAdd(&rowsum_s[wr * 16 + g], rs_lo);
        atomicAdd(&rowsum_s[wr * 16 + g + 8], rs_hi);
    }
    __syncthreads();

    if (tid < BM) g_invsum[r0 + tid] = 1.0f / rowsum_s[tid];

    float ilo = 1.0f / rowsum_s[rlo];
    float ihi = 1.0f / rowsum_s[rhi];
#pragma unroll
    for (int nt = 0; nt < 4; nt++) {
        int col = wc * 32 + nt * 8 + 2 * t;
        *reinterpret_cast<float2*>(&out_res[(size_t)(r0 + rlo) * D + col]) =
            make_float2(oacc[nt][0] * ilo, oacc[nt][1] * ilo);
        *reinterpret_cast<float2*>(&out_res[(size_t)(r0 + rhi) * D + col]) =
            make_float2(oacc[nt][2] * ihi, oacc[nt][3] * ihi);
    }
}

// ---------------------------------------------------------------------------
// Kernel 3: normalize stored p: p[row][:] *= 1/rowsum[row].
// ---------------------------------------------------------------------------
__global__ void rescale_kernel(float* __restrict__ p, int M) {
    int row  = blockIdx.y;
    int col4 = blockIdx.x * blockDim.x + threadIdx.x;
    int m4   = M >> 2;
    if (col4 >= m4) return;
    float inv = g_invsum[row];
    float4* p4 = reinterpret_cast<float4*>(p) + (size_t)row * m4 + col4;
    float4 v = *p4;
    v.x *= inv; v.y *= inv; v.z *= inv; v.w *= inv;
    *p4 = v;
}

// ---------------------------------------------------------------------------
extern "C" void kernel_launch(void* const* d_in, const int* in_sizes, int n_in,
                              void* d_out, int out_size) {
    const float* q  = (const float*)d_in[0];
    const float* k  = (const float*)d_in[1];
    const float* v  = (const float*)d_in[2];
    const int*   hc = (const int*)d_in[3];

    int N = in_sizes[0] / D;
    int M = in_sizes[1] / D;

    float* out_res = (float*)d_out;                      // [N, D]
    float* out_p   = (float*)d_out + (size_t)N * D;      // [N, M]

    int rows = N + M;
    int norm_blocks = (rows * 32 + 255) / 256;
    norm_kernel<<<norm_blocks, 256>>>(q, k, N, M);

    strip_kernel<<<N / BM, 128>>>(v, hc, out_res, out_p, N, M);

    dim3 rg((M / 4 + 255) / 256, N);
    rescale_kernel<<<rg, 256>>>(out_p, M);
}

// round 4
// speedup vs baseline: 4.3150x; 2.0137x over previous
#include <cuda_runtime.h>
#include <cuda_fp16.h>
#include <cstdint>
#include <math.h>

#define D     64
#define MAXN  8192
#define BM    64
#define BN    64
#define DPAD  72   // halves per smem row (144B): conflict-free ldmatrix

// Scratch (allocation-free contract: __device__ globals)
__device__ __align__(16) __half g_Qh[(size_t)MAXN * D];
__device__ __align__(16) __half g_Kh[(size_t)MAXN * D];
__device__ __align__(16) __half g_Vh[(size_t)MAXN * D];
__device__ float g_invsum[MAXN];

__device__ __forceinline__ float load_hyper_c(const int* hc) {
    int iv = hc[0];
    if (iv > 1000000 || iv < -1000000) return __int_as_float(iv);
    return (float)iv;
}

__device__ __forceinline__ uint32_t smem_u32(const void* p) {
    return (uint32_t)__cvta_generic_to_shared(p);
}

__device__ __forceinline__ void ldsm_x4(uint32_t& r0, uint32_t& r1,
                                        uint32_t& r2, uint32_t& r3,
                                        uint32_t addr) {
    asm volatile("ldmatrix.sync.aligned.m8n8.x4.shared.b16 {%0,%1,%2,%3}, [%4];\n"
                 : "=r"(r0), "=r"(r1), "=r"(r2), "=r"(r3) : "r"(addr));
}

__device__ __forceinline__ void ldsm_x4_trans(uint32_t& r0, uint32_t& r1,
                                              uint32_t& r2, uint32_t& r3,
                                              uint32_t addr) {
    asm volatile("ldmatrix.sync.aligned.m8n8.x4.trans.shared.b16 {%0,%1,%2,%3}, [%4];\n"
                 : "=r"(r0), "=r"(r1), "=r"(r2), "=r"(r3) : "r"(addr));
}

// D += A*B, m16n8k16, f16 inputs, f32 accum
__device__ __forceinline__ void mma_f16(float d[4], const uint32_t a[4],
                                        uint32_t b0, uint32_t b1) {
    asm volatile(
        "mma.sync.aligned.m16n8k16.row.col.f32.f16.f16.f32 "
        "{%0,%1,%2,%3}, {%4,%5,%6,%7}, {%8,%9}, {%0,%1,%2,%3};\n"
        : "+f"(d[0]), "+f"(d[1]), "+f"(d[2]), "+f"(d[3])
        : "r"(a[0]), "r"(a[1]), "r"(a[2]), "r"(a[3]), "r"(b0), "r"(b1));
}

__device__ __forceinline__ void cp_async16(uint32_t smem_dst, const void* gmem_src) {
    asm volatile("cp.async.cg.shared.global [%0], [%1], 16;\n"
                 :: "r"(smem_dst), "l"(gmem_src) : "memory");
}
__device__ __forceinline__ void cp_commit() {
    asm volatile("cp.async.commit_group;\n" ::: "memory");
}
__device__ __forceinline__ void cp_wait1() {
    asm volatile("cp.async.wait_group 1;\n" ::: "memory");
}
__device__ __forceinline__ void cp_wait0() {
    asm volatile("cp.async.wait_group 0;\n" ::: "memory");
}

// ---------------------------------------------------------------------------
// Kernel 1: normalize Q,K rows -> fp16; convert V -> fp16. One warp per row.
// ---------------------------------------------------------------------------
__global__ void prep_kernel(const float* __restrict__ q,
                            const float* __restrict__ k,
                            const float* __restrict__ v,
                            int N, int M) {
    int gw   = (blockIdx.x * blockDim.x + threadIdx.x) >> 5;
    int lane = threadIdx.x & 31;
    if (gw >= N + 2 * M) return;

    const float* src;
    __half* dst;
    bool nrm = true;
    if (gw < N)          { src = q + (size_t)gw * D;               dst = g_Qh + (size_t)gw * D; }
    else if (gw < N + M) { size_t r = gw - N;     src = k + r * D; dst = g_Kh + r * D; }
    else                 { size_t r = gw - N - M; src = v + r * D; dst = g_Vh + r * D; nrm = false; }

    float2 val = reinterpret_cast<const float2*>(src)[lane];
    float inv = 1.0f;
    if (nrm) {
        float ss = val.x * val.x + val.y * val.y;
#pragma unroll
        for (int o = 16; o > 0; o >>= 1) ss += __shfl_xor_sync(0xffffffffu, ss, o);
        inv = rsqrtf(ss);
    }
    reinterpret_cast<__half2*>(dst)[lane] = __floats2half2_rn(val.x * inv, val.y * inv);
}

// ---------------------------------------------------------------------------
// Kernel 2: strip of BM=64 rows. 8 warps: wr=wid>>1 (16-row group), wc=wid&1
// (32-key half of each BN=64 tile). fp16 mma m16n8k16; E stays in registers
// between QK and PV; p written straight from registers (unnormalized).
// cp.async double-buffered K/V tiles.
// ---------------------------------------------------------------------------
__global__ __launch_bounds__(256)
void strip_kernel(const int* __restrict__ hc,
                  float* __restrict__ out_res,
                  float* __restrict__ out_p,
                  int N, int M) {
    __shared__ __align__(16) __half Ks[2][BN * DPAD];
    __shared__ __align__(16) __half Vs[2][BN * DPAD];
    __shared__ float rowsum_s[BM];

    const int tid  = threadIdx.x;
    const int lane = tid & 31;
    const int wid  = tid >> 5;
    const int wr   = wid >> 1;     // 0..3 -> rows [wr*16, wr*16+16)
    const int wc   = wid & 1;      // 0..1 -> keys half [wc*32, wc*32+32)
    const int g    = lane >> 2;    // 0..7
    const int t    = lane & 3;     // 0..3
    const int r0   = blockIdx.x * BM;
    const float c  = load_hyper_c(hc);
    const int j    = lane >> 3;    // ldmatrix matrix id
    const int jr   = lane & 7;     // row within matrix

    if (tid < BM) rowsum_s[tid] = 0.0f;

    // ---- Stage Q tile in Ks[0], extract A-fragments, then free the buffer ----
#pragma unroll
    for (int w = 0; w < 2; w++) {
        int chunk = tid + w * 256;          // 0..511
        int row = chunk >> 3;
        int c8  = chunk & 7;
        uint4 val = reinterpret_cast<const uint4*>(g_Qh + (size_t)(r0 + row) * D)[c8];
        *reinterpret_cast<uint4*>(&Ks[0][row * DPAD + c8 * 8]) = val;
    }
    __syncthreads();

    uint32_t qa[4][4];
#pragma unroll
    for (int kc = 0; kc < 4; kc++) {
        int row = wr * 16 + (j & 1) * 8 + jr;
        int col = kc * 16 + (j >> 1) * 8;
        ldsm_x4(qa[kc][0], qa[kc][1], qa[kc][2], qa[kc][3],
                smem_u32(&Ks[0][row * DPAD + col]));
    }
    __syncthreads();

    float oacc[8][4];
#pragma unroll
    for (int i = 0; i < 8; i++) {
#pragma unroll
        for (int jj = 0; jj < 4; jj++) oacc[i][jj] = 0.0f;
    }
    float rs_lo = 0.0f;
    float rs_hi = 0.0f;

    const int T = M / BN;

    // prefetch tile 0
#pragma unroll
    for (int w = 0; w < 2; w++) {
        int chunk = tid + w * 256;
        int row = chunk >> 3;
        int c8  = chunk & 7;
        cp_async16(smem_u32(&Ks[0][row * DPAD + c8 * 8]), g_Kh + (size_t)row * D + c8 * 8);
        cp_async16(smem_u32(&Vs[0][row * DPAD + c8 * 8]), g_Vh + (size_t)row * D + c8 * 8);
    }
    cp_commit();

    for (int tt = 0; tt < T; tt++) {
        const int cur = tt & 1;
        const int m0  = tt * BN;

        if (tt + 1 < T) {
            const int nxt = cur ^ 1;
            const int mn  = (tt + 1) * BN;
#pragma unroll
            for (int w = 0; w < 2; w++) {
                int chunk = tid + w * 256;
                int row = chunk >> 3;
                int c8  = chunk & 7;
                cp_async16(smem_u32(&Ks[nxt][row * DPAD + c8 * 8]),
                           g_Kh + (size_t)(mn + row) * D + c8 * 8);
                cp_async16(smem_u32(&Vs[nxt][row * DPAD + c8 * 8]),
                           g_Vh + (size_t)(mn + row) * D + c8 * 8);
            }
            cp_commit();
            cp_wait1();
        } else {
            cp_wait0();
        }
        __syncthreads();

        // ---- QK: S[16 rows][32 keys] per warp ----
        float sacc[4][4];
#pragma unroll
        for (int i = 0; i < 4; i++) {
#pragma unroll
            for (int jj = 0; jj < 4; jj++) sacc[i][jj] = 0.0f;
        }

#pragma unroll
        for (int kc = 0; kc < 4; kc++) {
#pragma unroll
            for (int ntp = 0; ntp < 2; ntp++) {
                uint32_t b0, b1, b2, b3;
                int key = wc * 32 + (2 * ntp + (j >> 1)) * 8 + jr;
                int col = kc * 16 + (j & 1) * 8;
                ldsm_x4(b0, b1, b2, b3, smem_u32(&Ks[cur][key * DPAD + col]));
                mma_f16(sacc[2 * ntp + 0], qa[kc], b0, b1);
                mma_f16(sacc[2 * ntp + 1], qa[kc], b2, b3);
            }
        }

        // ---- exp, rowsum, pack E to fp16 regs, write unnormalized p ----
        uint32_t ea[4];
        uint32_t eb[4];
#pragma unroll
        for (int nt = 0; nt < 4; nt++) {
            float e0 = __expf(c * (sacc[nt][0] - 1.0f));
            float e1 = __expf(c * (sacc[nt][1] - 1.0f));
            float e2 = __expf(c * (sacc[nt][2] - 1.0f));
            float e3 = __expf(c * (sacc[nt][3] - 1.0f));
            rs_lo += e0 + e1;
            rs_hi += e2 + e3;
            __half2 hlo = __floats2half2_rn(e0, e1);
            __half2 hhi = __floats2half2_rn(e2, e3);
            ea[nt] = *reinterpret_cast<uint32_t*>(&hlo);
            eb[nt] = *reinterpret_cast<uint32_t*>(&hhi);
            int col   = m0 + wc * 32 + nt * 8 + 2 * t;
            int rowlo = r0 + wr * 16 + g;
            *reinterpret_cast<float2*>(out_p + (size_t)rowlo * M + col)       = make_float2(e0, e1);
            *reinterpret_cast<float2*>(out_p + (size_t)(rowlo + 8) * M + col) = make_float2(e2, e3);
        }

        // ---- PV: O[16 rows][64 d] += E(16x32) @ V(32x64) ----
#pragma unroll
        for (int kc2 = 0; kc2 < 2; kc2++) {
            uint32_t av[4];
            av[0] = ea[2 * kc2];
            av[1] = eb[2 * kc2];
            av[2] = ea[2 * kc2 + 1];
            av[3] = eb[2 * kc2 + 1];
#pragma unroll
            for (int dnp = 0; dnp < 4; dnp++) {
                uint32_t b0, b1, b2, b3;
                int key = wc * 32 + kc2 * 16 + (j & 1) * 8 + jr;
                int col = (2 * dnp + (j >> 1)) * 8;
                ldsm_x4_trans(b0, b1, b2, b3, smem_u32(&Vs[cur][key * DPAD + col]));
                mma_f16(oacc[2 * dnp + 0], av, b0, b1);
                mma_f16(oacc[2 * dnp + 1], av, b2, b3);
            }
        }
        __syncthreads();
    }

    // ---- rowsum: reduce over t lanes, combine wc halves via smem atomics ----
#pragma unroll
    for (int o = 1; o <= 2; o <<= 1) {
        rs_lo += __shfl_xor_sync(0xffffffffu, rs_lo, o);
        rs_hi += __shfl_xor_sync(0xffffffffu, rs_hi, o);
    }
    if (t == 0) {
        atomicAdd(&rowsum_s[wr * 16 + g], rs_lo);
        atomicAdd(&rowsum_s[wr * 16 + g + 8], rs_hi);
    }

    // ---- O cross-warp reduction: wc=1 publishes partials (reuse K/V smem) ----
    float* Osum = reinterpret_cast<float*>(&Ks[0][0]);   // [BM][64] floats = 16KB
    if (wc == 1) {
        int rowlo = wr * 16 + g;
#pragma unroll
        for (int dn = 0; dn < 8; dn++) {
            int col = dn * 8 + 2 * t;
            *reinterpret_cast<float2*>(&Osum[rowlo * 64 + col]) =
                make_float2(oacc[dn][0], oacc[dn][1]);
            *reinterpret_cast<float2*>(&Osum[(rowlo + 8) * 64 + col]) =
                make_float2(oacc[dn][2], oacc[dn][3]);
        }
    }
    __syncthreads();

    if (tid < BM) g_invsum[r0 + tid] = 1.0f / rowsum_s[tid];

    if (wc == 0) {
        int rowlo = wr * 16 + g;
        float ilo = 1.0f / rowsum_s[rowlo];
        float ihi = 1.0f / rowsum_s[rowlo + 8];
#pragma unroll
        for (int dn = 0; dn < 8; dn++) {
            int col = dn * 8 + 2 * t;
            float2 p1 = *reinterpret_cast<float2*>(&Osum[rowlo * 64 + col]);
            float2 p2 = *reinterpret_cast<float2*>(&Osum[(rowlo + 8) * 64 + col]);
            *reinterpret_cast<float2*>(out_res + (size_t)(r0 + rowlo) * D + col) =
                make_float2((oacc[dn][0] + p1.x) * ilo, (oacc[dn][1] + p1.y) * ilo);
            *reinterpret_cast<float2*>(out_res + (size_t)(r0 + rowlo + 8) * D + col) =
                make_float2((oacc[dn][2] + p2.x) * ihi, (oacc[dn][3] + p2.y) * ihi);
        }
    }
}

// ---------------------------------------------------------------------------
// Kernel 3: normalize stored p: p[row][:] *= 1/rowsum[row].
// ---------------------------------------------------------------------------
__global__ void rescale_kernel(float* __restrict__ p, int M) {
    int row  = blockIdx.y;
    int col4 = blockIdx.x * blockDim.x + threadIdx.x;
    int m4   = M >> 2;
    if (col4 >= m4) return;
    float inv = g_invsum[row];
    float4* p4 = reinterpret_cast<float4*>(p) + (size_t)row * m4 + col4;
    float4 v = *p4;
    v.x *= inv; v.y *= inv; v.z *= inv; v.w *= inv;
    *p4 = v;
}

// ---------------------------------------------------------------------------
extern "C" void kernel_launch(void* const* d_in, const int* in_sizes, int n_in,
                              void* d_out, int out_size) {
    const float* q  = (const float*)d_in[0];
    const float* k  = (const float*)d_in[1];
    const float* v  = (const float*)d_in[2];
    const int*   hc = (const int*)d_in[3];

    int N = in_sizes[0] / D;
    int M = in_sizes[1] / D;

    float* out_res = (float*)d_out;                      // [N, D]
    float* out_p   = (float*)d_out + (size_t)N * D;      // [N, M]

    int rows = N + 2 * M;
    int prep_blocks = (rows * 32 + 255) / 256;
    prep_kernel<<<prep_blocks, 256>>>(q, k, v, N, M);

    strip_kernel<<<N / BM, 256>>>(hc, out_res, out_p, N, M);

    dim3 rg((M / 4 + 255) / 256, N);
    rescale_kernel<<<rg, 256>>>(out_p, M);
}

// round 5
// speedup vs baseline: 4.9488x; 1.1469x over previous
#include <cuda_runtime.h>
#include <cuda_fp16.h>
#include <cstdint>
#include <math.h>

#define D     64
#define MAXN  8192
#define BM    64
#define BN    64
#define DPAD  72      // halves per smem row (144B): conflict-free ldmatrix
#define ESCALE    4096.0f
#define INV_ESCALE (1.0f / 4096.0f)

// Scratch (allocation-free contract: __device__ globals)
__device__ __align__(16) __half g_Qh[(size_t)MAXN * D];
__device__ __align__(16) __half g_Kh[(size_t)MAXN * D];
__device__ __align__(16) __half g_Vh[(size_t)MAXN * D];
__device__ float g_invsum[MAXN];

__device__ __forceinline__ float load_hyper_c(const int* hc) {
    int iv = hc[0];
    if (iv > 1000000 || iv < -1000000) return __int_as_float(iv);
    return (float)iv;
}

__device__ __forceinline__ uint32_t smem_u32(const void* p) {
    return (uint32_t)__cvta_generic_to_shared(p);
}

__device__ __forceinline__ void ldsm_x4(uint32_t& r0, uint32_t& r1,
                                        uint32_t& r2, uint32_t& r3,
                                        uint32_t addr) {
    asm volatile("ldmatrix.sync.aligned.m8n8.x4.shared.b16 {%0,%1,%2,%3}, [%4];\n"
                 : "=r"(r0), "=r"(r1), "=r"(r2), "=r"(r3) : "r"(addr));
}

__device__ __forceinline__ void ldsm_x4_trans(uint32_t& r0, uint32_t& r1,
                                              uint32_t& r2, uint32_t& r3,
                                              uint32_t addr) {
    asm volatile("ldmatrix.sync.aligned.m8n8.x4.trans.shared.b16 {%0,%1,%2,%3}, [%4];\n"
                 : "=r"(r0), "=r"(r1), "=r"(r2), "=r"(r3) : "r"(addr));
}

// D += A*B, m16n8k16, f16 inputs, f32 accum
__device__ __forceinline__ void mma_f16(float d[4], const uint32_t a[4],
                                        uint32_t b0, uint32_t b1) {
    asm volatile(
        "mma.sync.aligned.m16n8k16.row.col.f32.f16.f16.f32 "
        "{%0,%1,%2,%3}, {%4,%5,%6,%7}, {%8,%9}, {%0,%1,%2,%3};\n"
        : "+f"(d[0]), "+f"(d[1]), "+f"(d[2]), "+f"(d[3])
        : "r"(a[0]), "r"(a[1]), "r"(a[2]), "r"(a[3]), "r"(b0), "r"(b1));
}

__device__ __forceinline__ void cp_async16(uint32_t smem_dst, const void* gmem_src) {
    asm volatile("cp.async.cg.shared.global [%0], [%1], 16;\n"
                 :: "r"(smem_dst), "l"(gmem_src) : "memory");
}
__device__ __forceinline__ void cp_commit() {
    asm volatile("cp.async.commit_group;\n" ::: "memory");
}
__device__ __forceinline__ void cp_wait1() {
    asm volatile("cp.async.wait_group 1;\n" ::: "memory");
}
__device__ __forceinline__ void cp_wait0() {
    asm volatile("cp.async.wait_group 0;\n" ::: "memory");
}

// ---------------------------------------------------------------------------
// Kernel 1: normalize Q,K rows -> fp16; convert V -> fp16. One warp per row.
// ---------------------------------------------------------------------------
__global__ void prep_kernel(const float* __restrict__ q,
                            const float* __restrict__ k,
                            const float* __restrict__ v,
                            int N, int M) {
    int gw   = (blockIdx.x * blockDim.x + threadIdx.x) >> 5;
    int lane = threadIdx.x & 31;
    if (gw >= N + 2 * M) return;

    const float* src;
    __half* dst;
    bool nrm = true;
    if (gw < N)          { src = q + (size_t)gw * D;               dst = g_Qh + (size_t)gw * D; }
    else if (gw < N + M) { size_t r = gw - N;     src = k + r * D; dst = g_Kh + r * D; }
    else                 { size_t r = gw - N - M; src = v + r * D; dst = g_Vh + r * D; nrm = false; }

    float2 val = reinterpret_cast<const float2*>(src)[lane];
    float inv = 1.0f;
    if (nrm) {
        float ss = val.x * val.x + val.y * val.y;
#pragma unroll
        for (int o = 16; o > 0; o >>= 1) ss += __shfl_xor_sync(0xffffffffu, ss, o);
        inv = rsqrtf(ss);
    }
    reinterpret_cast<__half2*>(dst)[lane] = __floats2half2_rn(val.x * inv, val.y * inv);
}

// ---------------------------------------------------------------------------
// Kernel 2 (phase 1): rowsums only. Same QK structure as the strip kernel but
// no V, no PV, no p store. K is L2-resident (1 MB) so the recompute is cheap.
// Writes g_invsum[row] = 1/rowsum.
// ---------------------------------------------------------------------------
__global__ __launch_bounds__(256)
void sum_kernel(const int* __restrict__ hc, int N, int M) {
    __shared__ __align__(16) __half Ks[2][BN * DPAD];
    __shared__ float rowsum_s[BM];

    const int tid  = threadIdx.x;
    const int lane = tid & 31;
    const int wid  = tid >> 5;
    const int wr   = wid >> 1;
    const int wc   = wid & 1;
    const int g    = lane >> 2;
    const int t    = lane & 3;
    const int r0   = blockIdx.x * BM;
    const float c  = load_hyper_c(hc);
    const int j    = lane >> 3;
    const int jr   = lane & 7;

    if (tid < BM) rowsum_s[tid] = 0.0f;

    // Stage Q tile in Ks[0], extract A-fragments
#pragma unroll
    for (int w = 0; w < 2; w++) {
        int chunk = tid + w * 256;
        int row = chunk >> 3;
        int c8  = chunk & 7;
        uint4 val = reinterpret_cast<const uint4*>(g_Qh + (size_t)(r0 + row) * D)[c8];
        *reinterpret_cast<uint4*>(&Ks[0][row * DPAD + c8 * 8]) = val;
    }
    __syncthreads();

    uint32_t qa[4][4];
#pragma unroll
    for (int kc = 0; kc < 4; kc++) {
        int row = wr * 16 + (j & 1) * 8 + jr;
        int col = kc * 16 + (j >> 1) * 8;
        ldsm_x4(qa[kc][0], qa[kc][1], qa[kc][2], qa[kc][3],
                smem_u32(&Ks[0][row * DPAD + col]));
    }
    __syncthreads();

    float rs_lo = 0.0f;
    float rs_hi = 0.0f;
    const int T = M / BN;

    // prefetch K tile 0
#pragma unroll
    for (int w = 0; w < 2; w++) {
        int chunk = tid + w * 256;
        int row = chunk >> 3;
        int c8  = chunk & 7;
        cp_async16(smem_u32(&Ks[0][row * DPAD + c8 * 8]), g_Kh + (size_t)row * D + c8 * 8);
    }
    cp_commit();

    for (int tt = 0; tt < T; tt++) {
        const int cur = tt & 1;
        if (tt + 1 < T) {
            const int nxt = cur ^ 1;
            const int mn  = (tt + 1) * BN;
#pragma unroll
            for (int w = 0; w < 2; w++) {
                int chunk = tid + w * 256;
                int row = chunk >> 3;
                int c8  = chunk & 7;
                cp_async16(smem_u32(&Ks[nxt][row * DPAD + c8 * 8]),
                           g_Kh + (size_t)(mn + row) * D + c8 * 8);
            }
            cp_commit();
            cp_wait1();
        } else {
            cp_wait0();
        }
        __syncthreads();

        float sacc[4][4];
#pragma unroll
        for (int i = 0; i < 4; i++) {
#pragma unroll
            for (int jj = 0; jj < 4; jj++) sacc[i][jj] = 0.0f;
        }

#pragma unroll
        for (int kc = 0; kc < 4; kc++) {
#pragma unroll
            for (int ntp = 0; ntp < 2; ntp++) {
                uint32_t b0, b1, b2, b3;
                int key = wc * 32 + (2 * ntp + (j >> 1)) * 8 + jr;
                int col = kc * 16 + (j & 1) * 8;
                ldsm_x4(b0, b1, b2, b3, smem_u32(&Ks[cur][key * DPAD + col]));
                mma_f16(sacc[2 * ntp + 0], qa[kc], b0, b1);
                mma_f16(sacc[2 * ntp + 1], qa[kc], b2, b3);
            }
        }

#pragma unroll
        for (int nt = 0; nt < 4; nt++) {
            rs_lo += __expf(c * (sacc[nt][0] - 1.0f)) + __expf(c * (sacc[nt][1] - 1.0f));
            rs_hi += __expf(c * (sacc[nt][2] - 1.0f)) + __expf(c * (sacc[nt][3] - 1.0f));
        }
        __syncthreads();
    }

#pragma unroll
    for (int o = 1; o <= 2; o <<= 1) {
        rs_lo += __shfl_xor_sync(0xffffffffu, rs_lo, o);
        rs_hi += __shfl_xor_sync(0xffffffffu, rs_hi, o);
    }
    if (t == 0) {
        atomicAdd(&rowsum_s[wr * 16 + g], rs_lo);
        atomicAdd(&rowsum_s[wr * 16 + g + 8], rs_hi);
    }
    __syncthreads();

    if (tid < BM) g_invsum[r0 + tid] = 1.0f / rowsum_s[tid];
}

// ---------------------------------------------------------------------------
// Kernel 3 (phase 2): full pass. Uses precomputed invsum: writes NORMALIZED p
// directly (no rescale pass), feeds scaled-normalized E into PV, unscales O.
// ---------------------------------------------------------------------------
__global__ __launch_bounds__(256)
void strip_kernel(const int* __restrict__ hc,
                  float* __restrict__ out_res,
                  float* __restrict__ out_p,
                  int N, int M) {
    __shared__ __align__(16) __half Ks[2][BN * DPAD];
    __shared__ __align__(16) __half Vs[2][BN * DPAD];

    const int tid  = threadIdx.x;
    const int lane = tid & 31;
    const int wid  = tid >> 5;
    const int wr   = wid >> 1;
    const int wc   = wid & 1;
    const int g    = lane >> 2;
    const int t    = lane & 3;
    const int r0   = blockIdx.x * BM;
    const float c  = load_hyper_c(hc);
    const int j    = lane >> 3;
    const int jr   = lane & 7;

    const int rowlo = wr * 16 + g;
    const float inv_lo = g_invsum[r0 + rowlo];
    const float inv_hi = g_invsum[r0 + rowlo + 8];
    const float sc_lo  = inv_lo * ESCALE;
    const float sc_hi  = inv_hi * ESCALE;

    // Stage Q tile in Ks[0], extract A-fragments, then free the buffer
#pragma unroll
    for (int w = 0; w < 2; w++) {
        int chunk = tid + w * 256;
        int row = chunk >> 3;
        int c8  = chunk & 7;
        uint4 val = reinterpret_cast<const uint4*>(g_Qh + (size_t)(r0 + row) * D)[c8];
        *reinterpret_cast<uint4*>(&Ks[0][row * DPAD + c8 * 8]) = val;
    }
    __syncthreads();

    uint32_t qa[4][4];
#pragma unroll
    for (int kc = 0; kc < 4; kc++) {
        int row = wr * 16 + (j & 1) * 8 + jr;
        int col = kc * 16 + (j >> 1) * 8;
        ldsm_x4(qa[kc][0], qa[kc][1], qa[kc][2], qa[kc][3],
                smem_u32(&Ks[0][row * DPAD + col]));
    }
    __syncthreads();

    float oacc[8][4];
#pragma unroll
    for (int i = 0; i < 8; i++) {
#pragma unroll
        for (int jj = 0; jj < 4; jj++) oacc[i][jj] = 0.0f;
    }

    const int T = M / BN;

    // prefetch tile 0
#pragma unroll
    for (int w = 0; w < 2; w++) {
        int chunk = tid + w * 256;
        int row = chunk >> 3;
        int c8  = chunk & 7;
        cp_async16(smem_u32(&Ks[0][row * DPAD + c8 * 8]), g_Kh + (size_t)row * D + c8 * 8);
        cp_async16(smem_u32(&Vs[0][row * DPAD + c8 * 8]), g_Vh + (size_t)row * D + c8 * 8);
    }
    cp_commit();

    for (int tt = 0; tt < T; tt++) {
        const int cur = tt & 1;
        const int m0  = tt * BN;

        if (tt + 1 < T) {
            const int nxt = cur ^ 1;
            const int mn  = (tt + 1) * BN;
#pragma unroll
            for (int w = 0; w < 2; w++) {
                int chunk = tid + w * 256;
                int row = chunk >> 3;
                int c8  = chunk & 7;
                cp_async16(smem_u32(&Ks[nxt][row * DPAD + c8 * 8]),
                           g_Kh + (size_t)(mn + row) * D + c8 * 8);
                cp_async16(smem_u32(&Vs[nxt][row * DPAD + c8 * 8]),
                           g_Vh + (size_t)(mn + row) * D + c8 * 8);
            }
            cp_commit();
            cp_wait1();
        } else {
            cp_wait0();
        }
        __syncthreads();

        // ---- QK ----
        float sacc[4][4];
#pragma unroll
        for (int i = 0; i < 4; i++) {
#pragma unroll
            for (int jj = 0; jj < 4; jj++) sacc[i][jj] = 0.0f;
        }

#pragma unroll
        for (int kc = 0; kc < 4; kc++) {
#pragma unroll
            for (int ntp = 0; ntp < 2; ntp++) {
                uint32_t b0, b1, b2, b3;
                int key = wc * 32 + (2 * ntp + (j >> 1)) * 8 + jr;
                int col = kc * 16 + (j & 1) * 8;
                ldsm_x4(b0, b1, b2, b3, smem_u32(&Ks[cur][key * DPAD + col]));
                mma_f16(sacc[2 * ntp + 0], qa[kc], b0, b1);
                mma_f16(sacc[2 * ntp + 1], qa[kc], b2, b3);
            }
        }

        // ---- exp, write normalized p, pack scaled-normalized E ----
        uint32_t ea[4];
        uint32_t eb[4];
#pragma unroll
        for (int nt = 0; nt < 4; nt++) {
            float e0 = __expf(c * (sacc[nt][0] - 1.0f));
            float e1 = __expf(c * (sacc[nt][1] - 1.0f));
            float e2 = __expf(c * (sacc[nt][2] - 1.0f));
            float e3 = __expf(c * (sacc[nt][3] - 1.0f));
            __half2 hlo = __floats2half2_rn(e0 * sc_lo, e1 * sc_lo);
            __half2 hhi = __floats2half2_rn(e2 * sc_hi, e3 * sc_hi);
            ea[nt] = *reinterpret_cast<uint32_t*>(&hlo);
            eb[nt] = *reinterpret_cast<uint32_t*>(&hhi);
            int col = m0 + wc * 32 + nt * 8 + 2 * t;
            *reinterpret_cast<float2*>(out_p + (size_t)(r0 + rowlo) * M + col) =
                make_float2(e0 * inv_lo, e1 * inv_lo);
            *reinterpret_cast<float2*>(out_p + (size_t)(r0 + rowlo + 8) * M + col) =
                make_float2(e2 * inv_hi, e3 * inv_hi);
        }

        // ---- PV ----
#pragma unroll
        for (int kc2 = 0; kc2 < 2; kc2++) {
            uint32_t av[4];
            av[0] = ea[2 * kc2];
            av[1] = eb[2 * kc2];
            av[2] = ea[2 * kc2 + 1];
            av[3] = eb[2 * kc2 + 1];
#pragma unroll
            for (int dnp = 0; dnp < 4; dnp++) {
                uint32_t b0, b1, b2, b3;
                int key = wc * 32 + kc2 * 16 + (j & 1) * 8 + jr;
                int col = (2 * dnp + (j >> 1)) * 8;
                ldsm_x4_trans(b0, b1, b2, b3, smem_u32(&Vs[cur][key * DPAD + col]));
                mma_f16(oacc[2 * dnp + 0], av, b0, b1);
                mma_f16(oacc[2 * dnp + 1], av, b2, b3);
            }
        }
        __syncthreads();
    }

    // ---- O cross-warp reduction (wc halves), unscale, store ----
    float* Osum = reinterpret_cast<float*>(&Ks[0][0]);   // [BM][64] floats = 16KB
    if (wc == 1) {
#pragma unroll
        for (int dn = 0; dn < 8; dn++) {
            int col = dn * 8 + 2 * t;
            *reinterpret_cast<float2*>(&Osum[rowlo * 64 + col]) =
                make_float2(oacc[dn][0], oacc[dn][1]);
            *reinterpret_cast<float2*>(&Osum[(rowlo + 8) * 64 + col]) =
                make_float2(oacc[dn][2], oacc[dn][3]);
        }
    }
    __syncthreads();

    if (wc == 0) {
#pragma unroll
        for (int dn = 0; dn < 8; dn++) {
            int col = dn * 8 + 2 * t;
            float2 p1 = *reinterpret_cast<float2*>(&Osum[rowlo * 64 + col]);
            float2 p2 = *reinterpret_cast<float2*>(&Osum[(rowlo + 8) * 64 + col]);
            *reinterpret_cast<float2*>(out_res + (size_t)(r0 + rowlo) * D + col) =
                make_float2((oacc[dn][0] + p1.x) * INV_ESCALE,
                            (oacc[dn][1] + p1.y) * INV_ESCALE);
            *reinterpret_cast<float2*>(out_res + (size_t)(r0 + rowlo + 8) * D + col) =
                make_float2((oacc[dn][2] + p2.x) * INV_ESCALE,
                            (oacc[dn][3] + p2.y) * INV_ESCALE);
        }
    }
}

// ---------------------------------------------------------------------------
extern "C" void kernel_launch(void* const* d_in, const int* in_sizes, int n_in,
                              void* d_out, int out_size) {
    const float* q  = (const float*)d_in[0];
    const float* k  = (const float*)d_in[1];
    const float* v  = (const float*)d_in[2];
    const int*   hc = (const int*)d_in[3];

    int N = in_sizes[0] / D;
    int M = in_sizes[1] / D;

    float* out_res = (float*)d_out;                      // [N, D]
    float* out_p   = (float*)d_out + (size_t)N * D;      // [N, M]

    int rows = N + 2 * M;
    int prep_blocks = (rows * 32 + 255) / 256;
    prep_kernel<<<prep_blocks, 256>>>(q, k, v, N, M);

    sum_kernel<<<N / BM, 256>>>(hc, N, M);

    strip_kernel<<<N / BM, 256>>>(hc, out_res, out_p, N, M);
}

// round 6
// speedup vs baseline: 5.4681x; 1.1049x over previous
#include <cuda_runtime.h>
#include <cuda_fp16.h>
#include <cstdint>
#include <math.h>

#define D     64
#define MAXN  8192
#define BM    64
#define BN    128
#define ESCALE     4096.0f
#define INV_ESCALE (1.0f / 4096.0f)

// Scratch (allocation-free contract: __device__ globals)
__device__ __align__(16) __half g_Qh[(size_t)MAXN * D];
__device__ __align__(16) __half g_Kh[(size_t)MAXN * D];
__device__ __align__(16) __half g_Vh[(size_t)MAXN * D];
__device__ float g_invsum[MAXN];

__device__ __forceinline__ float load_hyper_c(const int* hc) {
    int iv = hc[0];
    if (iv > 1000000 || iv < -1000000) return __int_as_float(iv);
    return (float)iv;
}

__device__ __forceinline__ uint32_t smem_u32(const void* p) {
    return (uint32_t)__cvta_generic_to_shared(p);
}

// Swizzled byte offset inside a tile whose rows are 128B (64 halves).
// colbyte must be a multiple of 16. Conflict-free for cp.async row stores
// and ldmatrix column reads.
__device__ __forceinline__ uint32_t swz(int row, int colbyte) {
    return (uint32_t)(row * 128 + (colbyte ^ ((row & 7) << 4)));
}

__device__ __forceinline__ void ldsm_x4(uint32_t& r0, uint32_t& r1,
                                        uint32_t& r2, uint32_t& r3,
                                        uint32_t addr) {
    asm volatile("ldmatrix.sync.aligned.m8n8.x4.shared.b16 {%0,%1,%2,%3}, [%4];\n"
                 : "=r"(r0), "=r"(r1), "=r"(r2), "=r"(r3) : "r"(addr));
}

__device__ __forceinline__ void ldsm_x4_trans(uint32_t& r0, uint32_t& r1,
                                              uint32_t& r2, uint32_t& r3,
                                              uint32_t addr) {
    asm volatile("ldmatrix.sync.aligned.m8n8.x4.trans.shared.b16 {%0,%1,%2,%3}, [%4];\n"
                 : "=r"(r0), "=r"(r1), "=r"(r2), "=r"(r3) : "r"(addr));
}

__device__ __forceinline__ void mma_f16(float d[4], const uint32_t a[4],
                                        uint32_t b0, uint32_t b1) {
    asm volatile(
        "mma.sync.aligned.m16n8k16.row.col.f32.f16.f16.f32 "
        "{%0,%1,%2,%3}, {%4,%5,%6,%7}, {%8,%9}, {%0,%1,%2,%3};\n"
        : "+f"(d[0]), "+f"(d[1]), "+f"(d[2]), "+f"(d[3])
        : "r"(a[0]), "r"(a[1]), "r"(a[2]), "r"(a[3]), "r"(b0), "r"(b1));
}

__device__ __forceinline__ void cp_async16(uint32_t smem_dst, const void* gmem_src) {
    asm volatile("cp.async.cg.shared.global [%0], [%1], 16;\n"
                 :: "r"(smem_dst), "l"(gmem_src) : "memory");
}
__device__ __forceinline__ void cp_commit() {
    asm volatile("cp.async.commit_group;\n" ::: "memory");
}
__device__ __forceinline__ void cp_wait1() {
    asm volatile("cp.async.wait_group 1;\n" ::: "memory");
}
__device__ __forceinline__ void cp_wait0() {
    asm volatile("cp.async.wait_group 0;\n" ::: "memory");
}

// ---------------------------------------------------------------------------
// Kernel 1: normalize Q,K rows -> fp16; convert V -> fp16. One warp per row.
// ---------------------------------------------------------------------------
__global__ void prep_kernel(const float* __restrict__ q,
                            const float* __restrict__ k,
                            const float* __restrict__ v,
                            int N, int M) {
    int gw   = (blockIdx.x * blockDim.x + threadIdx.x) >> 5;
    int lane = threadIdx.x & 31;
    if (gw >= N + 2 * M) return;

    const float* src;
    __half* dst;
    bool nrm = true;
    if (gw < N)          { src = q + (size_t)gw * D;               dst = g_Qh + (size_t)gw * D; }
    else if (gw < N + M) { size_t r = gw - N;     src = k + r * D; dst = g_Kh + r * D; }
    else                 { size_t r = gw - N - M; src = v + r * D; dst = g_Vh + r * D; nrm = false; }

    float2 val = reinterpret_cast<const float2*>(src)[lane];
    float inv = 1.0f;
    if (nrm) {
        float ss = val.x * val.x + val.y * val.y;
#pragma unroll
        for (int o = 16; o > 0; o >>= 1) ss += __shfl_xor_sync(0xffffffffu, ss, o);
        inv = rsqrtf(ss);
    }
    reinterpret_cast<__half2*>(dst)[lane] = __floats2half2_rn(val.x * inv, val.y * inv);
}

// ---------------------------------------------------------------------------
// Kernel 2 (phase 1): rowsums only. BM=64 rows x BN=128 key tiles.
// 8 warps = 2 row-groups (32 rows) x 4 key-groups (32 keys).
// ---------------------------------------------------------------------------
__global__ __launch_bounds__(256)
void sum_kernel(const int* __restrict__ hc, int N, int M) {
    __shared__ __align__(16) char Kb[2][BN * 128];   // 2 x 16KB, swizzled
    __shared__ float rowsum_s[BM];

    const int tid  = threadIdx.x;
    const int lane = tid & 31;
    const int wid  = tid >> 5;
    const int rg   = wid >> 2;     // 0..1: rows [rg*32, rg*32+32)
    const int kg   = wid & 3;      // 0..3: keys [kg*32, kg*32+32)
    const int g    = lane >> 2;
    const int t    = lane & 3;
    const int j    = lane >> 3;
    const int jr   = lane & 7;
    const int r0   = blockIdx.x * BM;
    const float c  = load_hyper_c(hc);

    const uint32_t kb0 = smem_u32(&Kb[0][0]);
    const uint32_t kb1 = smem_u32(&Kb[1][0]);

    if (tid < BM) rowsum_s[tid] = 0.0f;

    // prefetch K tile 0 into Kb[0]
#pragma unroll
    for (int w = 0; w < 4; w++) {
        int chunk = tid + w * 256;          // 0..1023
        int row = chunk >> 3, c8 = chunk & 7;
        cp_async16(kb0 + swz(row, c8 * 16), g_Kh + (size_t)row * D + c8 * 8);
    }
    cp_commit();

    // stage Q (64 rows) into Kb[1], extract A-fragments
#pragma unroll
    for (int w = 0; w < 2; w++) {
        int chunk = tid + w * 256;          // 0..511
        int row = chunk >> 3, c8 = chunk & 7;
        uint4 val = reinterpret_cast<const uint4*>(g_Qh + (size_t)(r0 + row) * D)[c8];
        *reinterpret_cast<uint4*>(&Kb[1][swz(row, c8 * 16)]) = val;
    }
    __syncthreads();

    uint32_t qa[4][2][4];
#pragma unroll
    for (int kc = 0; kc < 4; kc++) {
#pragma unroll
        for (int f = 0; f < 2; f++) {
            int row = rg * 32 + f * 16 + (j & 1) * 8 + jr;
            int col = kc * 16 + (j >> 1) * 8;
            ldsm_x4(qa[kc][f][0], qa[kc][f][1], qa[kc][f][2], qa[kc][f][3],
                    kb1 + swz(row, col * 2));
        }
    }
    __syncthreads();

    float rs[2][2] = {{0.f, 0.f}, {0.f, 0.f}};
    const int T = M / BN;

    for (int tt = 0; tt < T; tt++) {
        const uint32_t cb = (tt & 1) ? kb1 : kb0;
        if (tt + 1 < T) {
            const uint32_t nb = (tt & 1) ? kb0 : kb1;
            const int mn = (tt + 1) * BN;
#pragma unroll
            for (int w = 0; w < 4; w++) {
                int chunk = tid + w * 256;
                int row = chunk >> 3, c8 = chunk & 7;
                cp_async16(nb + swz(row, c8 * 16), g_Kh + (size_t)(mn + row) * D + c8 * 8);
            }
            cp_commit();
            cp_wait1();
        } else {
            cp_wait0();
        }
        __syncthreads();

        float sacc[2][4][4];
#pragma unroll
        for (int f = 0; f < 2; f++)
#pragma unroll
            for (int nt = 0; nt < 4; nt++)
#pragma unroll
                for (int jj = 0; jj < 4; jj++) sacc[f][nt][jj] = 0.0f;

#pragma unroll
        for (int kc = 0; kc < 4; kc++) {
#pragma unroll
            for (int ntp = 0; ntp < 2; ntp++) {
                uint32_t b0, b1, b2, b3;
                int key = kg * 32 + (2 * ntp + (j >> 1)) * 8 + jr;
                int col = kc * 16 + (j & 1) * 8;
                ldsm_x4(b0, b1, b2, b3, cb + swz(key, col * 2));
#pragma unroll
                for (int f = 0; f < 2; f++) {
                    mma_f16(sacc[f][2 * ntp + 0], qa[kc][f], b0, b1);
                    mma_f16(sacc[f][2 * ntp + 1], qa[kc][f], b2, b3);
                }
            }
        }

#pragma unroll
        for (int f = 0; f < 2; f++) {
#pragma unroll
            for (int nt = 0; nt < 4; nt++) {
                rs[f][0] += __expf(c * (sacc[f][nt][0] - 1.0f)) +
                            __expf(c * (sacc[f][nt][1] - 1.0f));
                rs[f][1] += __expf(c * (sacc[f][nt][2] - 1.0f)) +
                            __expf(c * (sacc[f][nt][3] - 1.0f));
            }
        }
        __syncthreads();
    }

#pragma unroll
    for (int f = 0; f < 2; f++) {
#pragma unroll
        for (int o = 1; o <= 2; o <<= 1) {
            rs[f][0] += __shfl_xor_sync(0xffffffffu, rs[f][0], o);
            rs[f][1] += __shfl_xor_sync(0xffffffffu, rs[f][1], o);
        }
        if (t == 0) {
            atomicAdd(&rowsum_s[rg * 32 + f * 16 + g], rs[f][0]);
            atomicAdd(&rowsum_s[rg * 32 + f * 16 + g + 8], rs[f][1]);
        }
    }
    __syncthreads();

    if (tid < BM) g_invsum[r0 + tid] = 1.0f / rowsum_s[tid];
}

// ---------------------------------------------------------------------------
// Kernel 3 (phase 2): full pass, normalized p direct write, O via scaled E.
// Dynamic smem: Kb[2] (0, 16KB), Vb[2] (32KB, 48KB) = 64KB.
// ---------------------------------------------------------------------------
__global__ __launch_bounds__(256)
void strip_kernel(const int* __restrict__ hc,
                  float* __restrict__ out_res,
                  float* __restrict__ out_p,
                  int N, int M) {
    extern __shared__ __align__(16) char smem_raw[];
    const uint32_t sb = smem_u32(smem_raw);
    const uint32_t kOff[2] = {0u, 16384u};
    const uint32_t vOff[2] = {32768u, 49152u};

    const int tid  = threadIdx.x;
    const int lane = tid & 31;
    const int wid  = tid >> 5;
    const int rg   = wid >> 2;     // 0..1
    const int kg   = wid & 3;      // 0..3
    const int g    = lane >> 2;
    const int t    = lane & 3;
    const int j    = lane >> 3;
    const int jr   = lane & 7;
    const int r0   = blockIdx.x * BM;
    const float c  = load_hyper_c(hc);

    float inv[2][2], sc[2][2];
#pragma unroll
    for (int f = 0; f < 2; f++) {
        inv[f][0] = g_invsum[r0 + rg * 32 + f * 16 + g];
        inv[f][1] = g_invsum[r0 + rg * 32 + f * 16 + g + 8];
        sc[f][0] = inv[f][0] * ESCALE;
        sc[f][1] = inv[f][1] * ESCALE;
    }

    // prefetch K0/V0
#pragma unroll
    for (int w = 0; w < 4; w++) {
        int chunk = tid + w * 256;
        int row = chunk >> 3, c8 = chunk & 7;
        cp_async16(sb + kOff[0] + swz(row, c8 * 16), g_Kh + (size_t)row * D + c8 * 8);
        cp_async16(sb + vOff[0] + swz(row, c8 * 16), g_Vh + (size_t)row * D + c8 * 8);
    }
    cp_commit();

    // stage Q into Vb[1] region, extract A-fragments
#pragma unroll
    for (int w = 0; w < 2; w++) {
        int chunk = tid + w * 256;
        int row = chunk >> 3, c8 = chunk & 7;
        uint4 val = reinterpret_cast<const uint4*>(g_Qh + (size_t)(r0 + row) * D)[c8];
        *reinterpret_cast<uint4*>(smem_raw + vOff[1] + swz(row, c8 * 16)) = val;
    }
    __syncthreads();

    uint32_t qa[4][2][4];
#pragma unroll
    for (int kc = 0; kc < 4; kc++) {
#pragma unroll
        for (int f = 0; f < 2; f++) {
            int row = rg * 32 + f * 16 + (j & 1) * 8 + jr;
            int col = kc * 16 + (j >> 1) * 8;
            ldsm_x4(qa[kc][f][0], qa[kc][f][1], qa[kc][f][2], qa[kc][f][3],
                    sb + vOff[1] + swz(row, col * 2));
        }
    }
    __syncthreads();

    float oacc[2][8][4];
#pragma unroll
    for (int f = 0; f < 2; f++)
#pragma unroll
        for (int dn = 0; dn < 8; dn++)
#pragma unroll
            for (int jj = 0; jj < 4; jj++) oacc[f][dn][jj] = 0.0f;

    const int T = M / BN;

    for (int tt = 0; tt < T; tt++) {
        const int cur = tt & 1;
        const int m0  = tt * BN;

        if (tt + 1 < T) {
            const int nxt = cur ^ 1;
            const int mn  = (tt + 1) * BN;
#pragma unroll
            for (int w = 0; w < 4; w++) {
                int chunk = tid + w * 256;
                int row = chunk >> 3, c8 = chunk & 7;
                cp_async16(sb + kOff[nxt] + swz(row, c8 * 16),
                           g_Kh + (size_t)(mn + row) * D + c8 * 8);
                cp_async16(sb + vOff[nxt] + swz(row, c8 * 16),
                           g_Vh + (size_t)(mn + row) * D + c8 * 8);
            }
            cp_commit();
            cp_wait1();
        } else {
            cp_wait0();
        }
        __syncthreads();

        // ---- QK ----
        float sacc[2][4][4];
#pragma unroll
        for (int f = 0; f < 2; f++)
#pragma unroll
            for (int nt = 0; nt < 4; nt++)
#pragma unroll
                for (int jj = 0; jj < 4; jj++) sacc[f][nt][jj] = 0.0f;

#pragma unroll
        for (int kc = 0; kc < 4; kc++) {
#pragma unroll
            for (int ntp = 0; ntp < 2; ntp++) {
                uint32_t b0, b1, b2, b3;
                int key = kg * 32 + (2 * ntp + (j >> 1)) * 8 + jr;
                int col = kc * 16 + (j & 1) * 8;
                ldsm_x4(b0, b1, b2, b3, sb + kOff[cur] + swz(key, col * 2));
#pragma unroll
                for (int f = 0; f < 2; f++) {
                    mma_f16(sacc[f][2 * ntp + 0], qa[kc][f], b0, b1);
                    mma_f16(sacc[f][2 * ntp + 1], qa[kc][f], b2, b3);
                }
            }
        }

        // ---- exp, write normalized p, pack scaled-normalized E ----
        uint32_t ea[2][4], eb[2][4];
#pragma unroll
        for (int f = 0; f < 2; f++) {
            int rowlo = r0 + rg * 32 + f * 16 + g;
#pragma unroll
            for (int nt = 0; nt < 4; nt++) {
                float e0 = __expf(c * (sacc[f][nt][0] - 1.0f));
                float e1 = __expf(c * (sacc[f][nt][1] - 1.0f));
                float e2 = __expf(c * (sacc[f][nt][2] - 1.0f));
                float e3 = __expf(c * (sacc[f][nt][3] - 1.0f));
                __half2 hlo = __floats2half2_rn(e0 * sc[f][0], e1 * sc[f][0]);
                __half2 hhi = __floats2half2_rn(e2 * sc[f][1], e3 * sc[f][1]);
                ea[f][nt] = *reinterpret_cast<uint32_t*>(&hlo);
                eb[f][nt] = *reinterpret_cast<uint32_t*>(&hhi);
                int col = m0 + kg * 32 + nt * 8 + 2 * t;
                *reinterpret_cast<float2*>(out_p + (size_t)rowlo * M + col) =
                    make_float2(e0 * inv[f][0], e1 * inv[f][0]);
                *reinterpret_cast<float2*>(out_p + (size_t)(rowlo + 8) * M + col) =
                    make_float2(e2 * inv[f][1], e3 * inv[f][1]);
            }
        }

        // ---- PV ----
#pragma unroll
        for (int kc2 = 0; kc2 < 2; kc2++) {
#pragma unroll
            for (int dnp = 0; dnp < 4; dnp++) {
                uint32_t b0, b1, b2, b3;
                int key = kg * 32 + kc2 * 16 + (j & 1) * 8 + jr;
                int col = (2 * dnp + (j >> 1)) * 8;
                ldsm_x4_trans(b0, b1, b2, b3, sb + vOff[cur] + swz(key, col * 2));
#pragma unroll
                for (int f = 0; f < 2; f++) {
                    uint32_t av[4];
                    av[0] = ea[f][2 * kc2];
                    av[1] = eb[f][2 * kc2];
                    av[2] = ea[f][2 * kc2 + 1];
                    av[3] = eb[f][2 * kc2 + 1];
                    mma_f16(oacc[f][2 * dnp + 0], av, b0, b1);
                    mma_f16(oacc[f][2 * dnp + 1], av, b2, b3);
                }
            }
        }
        __syncthreads();
    }

    // ---- O reduction across 4 key-groups: kg=1..3 publish 16KB partials ----
    float* pbuf = reinterpret_cast<float*>(smem_raw);   // 3 x [64][64] floats
    if (kg != 0) {
        float* buf = pbuf + (size_t)(kg - 1) * 4096;
#pragma unroll
        for (int f = 0; f < 2; f++) {
            int rowlo = rg * 32 + f * 16 + g;
#pragma unroll
            for (int dn = 0; dn < 8; dn++) {
                int col = dn * 8 + 2 * t;
                *reinterpret_cast<float2*>(&buf[rowlo * 64 + col]) =
                    make_float2(oacc[f][dn][0], oacc[f][dn][1]);
                *reinterpret_cast<float2*>(&buf[(rowlo + 8) * 64 + col]) =
                    make_float2(oacc[f][dn][2], oacc[f][dn][3]);
            }
        }
    }
    __syncthreads();

    if (kg == 0) {
#pragma unroll
        for (int f = 0; f < 2; f++) {
            int rowlo = rg * 32 + f * 16 + g;
#pragma unroll
            for (int dn = 0; dn < 8; dn++) {
                int col = dn * 8 + 2 * t;
                float2 s1 = *reinterpret_cast<float2*>(&pbuf[0 * 4096 + rowlo * 64 + col]);
                float2 s2 = *reinterpret_cast<float2*>(&pbuf[1 * 4096 + rowlo * 64 + col]);
                float2 s3 = *reinterpret_cast<float2*>(&pbuf[2 * 4096 + rowlo * 64 + col]);
                float2 u1 = *reinterpret_cast<float2*>(&pbuf[0 * 4096 + (rowlo + 8) * 64 + col]);
                float2 u2 = *reinterpret_cast<float2*>(&pbuf[1 * 4096 + (rowlo + 8) * 64 + col]);
                float2 u3 = *reinterpret_cast<float2*>(&pbuf[2 * 4096 + (rowlo + 8) * 64 + col]);
                *reinterpret_cast<float2*>(out_res + (size_t)(r0 + rowlo) * D + col) =
                    make_float2((oacc[f][dn][0] + s1.x + s2.x + s3.x) * INV_ESCALE,
                                (oacc[f][dn][1] + s1.y + s2.y + s3.y) * INV_ESCALE);
                *reinterpret_cast<float2*>(out_res + (size_t)(r0 + rowlo + 8) * D + col) =
                    make_float2((oacc[f][dn][2] + u1.x + u2.x + u3.x) * INV_ESCALE,
                                (oacc[f][dn][3] + u1.y + u2.y + u3.y) * INV_ESCALE);
            }
        }
    }
}

// ---------------------------------------------------------------------------
extern "C" void kernel_launch(void* const* d_in, const int* in_sizes, int n_in,
                              void* d_out, int out_size) {
    const float* q  = (const float*)d_in[0];
    const float* k  = (const float*)d_in[1];
    const float* v  = (const float*)d_in[2];
    const int*   hc = (const int*)d_in[3];

    int N = in_sizes[0] / D;
    int M = in_sizes[1] / D;

    float* out_res = (float*)d_out;                      // [N, D]
    float* out_p   = (float*)d_out + (size_t)N * D;      // [N, M]

    int rows = N + 2 * M;
    int prep_blocks = (rows * 32 + 255) / 256;
    prep_kernel<<<prep_blocks, 256>>>(q, k, v, N, M);

    sum_kernel<<<N / BM, 256>>>(hc, N, M);

    static bool attr_set = false;
    if (!attr_set) {
        cudaFuncSetAttribute(strip_kernel,
                             cudaFuncAttributeMaxDynamicSharedMemorySize, 65536);
        attr_set = true;
    }
    strip_kernel<<<N / BM, 256, 65536>>>(hc, out_res, out_p, N, M);
}